// round 2
// baseline (speedup 1.0000x reference)
#include <cuda_runtime.h>
#include <cstdint>
#include <cstddef>

// ---------------------------------------------------------------------------
// PolicyHead round 2:
//   kernel 1: out = relu(x@W1^T+b1)           (pipelined tf32 mma GEMM)
//   kernel 2 (fused, per 64-row block):
//       q = out_b@W2^T+b2 ; k = out_b@W3^T+b3  (in-smem, weights from L2)
//       logits = q@k^T * SCALE ; promo ; gather(1858)
// Removes the 1.07GB q/k global round trip and pipelines all global loads.
// ---------------------------------------------------------------------------

#define HDIM 256
#define MROWS_MAX 262144
#define PSCALE 0.0625f

__device__ float g_out[(size_t)MROWS_MAX * HDIM];

__device__ __forceinline__ unsigned f2tf(float f) {
    unsigned r;
    asm("cvt.rna.tf32.f32 %0, %1;" : "=r"(r) : "f"(f));
    return r;
}

__device__ __forceinline__ void mma8(float* d, const unsigned* a, const unsigned* b) {
    asm volatile(
        "mma.sync.aligned.m16n8k8.row.col.f32.tf32.tf32.f32 "
        "{%0,%1,%2,%3}, {%4,%5,%6,%7}, {%8,%9}, {%0,%1,%2,%3};\n"
        : "+f"(d[0]), "+f"(d[1]), "+f"(d[2]), "+f"(d[3])
        : "r"(a[0]), "r"(a[1]), "r"(a[2]), "r"(a[3]), "r"(b[0]), "r"(b[1]));
}

// ---------------------------------------------------------------------------
// GEMM1: C = relu(A[M,256] @ W[256,256]^T + b). Tile 128x128, 8 warps,
// BK=32, register-staged software pipeline (LDG next chunk during mma).
// ---------------------------------------------------------------------------
__global__ __launch_bounds__(256, 2)
void gemm1_kernel(const float* __restrict__ A, const float* __restrict__ W,
                  const float* __restrict__ bias, float* __restrict__ C) {
    __shared__ unsigned As[128 * 36];
    __shared__ unsigned Bs[128 * 36];
    const int m0 = blockIdx.y * 128;
    const int n0 = blockIdx.x * 128;
    const int tid = threadIdx.x;
    const int warp = tid >> 5, lane = tid & 31;
    const int g = lane >> 2, t = lane & 3;
    const int wm = warp >> 1, wn = warp & 1;

    float acc[2][8][4];
#pragma unroll
    for (int i = 0; i < 2; i++)
#pragma unroll
        for (int j = 0; j < 8; j++)
#pragma unroll
            for (int l = 0; l < 4; l++) acc[i][j][l] = 0.f;

    const int lrow = tid >> 3;
    const int lcol = (tid & 7) * 4;

    float4 ra[4], rb[4];
#pragma unroll
    for (int i = 0; i < 4; i++) {
        int row = lrow + i * 32;
        ra[i] = *(const float4*)(A + (size_t)(m0 + row) * HDIM + lcol);
        rb[i] = *(const float4*)(W + (size_t)(n0 + row) * HDIM + lcol);
    }

    for (int k0 = 0; k0 < HDIM; k0 += 32) {
#pragma unroll
        for (int i = 0; i < 4; i++) {
            int row = lrow + i * 32;
            *(uint4*)&As[row * 36 + lcol] =
                make_uint4(f2tf(ra[i].x), f2tf(ra[i].y), f2tf(ra[i].z), f2tf(ra[i].w));
            *(uint4*)&Bs[row * 36 + lcol] =
                make_uint4(f2tf(rb[i].x), f2tf(rb[i].y), f2tf(rb[i].z), f2tf(rb[i].w));
        }
        __syncthreads();
        if (k0 + 32 < HDIM) {
#pragma unroll
            for (int i = 0; i < 4; i++) {
                int row = lrow + i * 32;
                ra[i] = *(const float4*)(A + (size_t)(m0 + row) * HDIM + k0 + 32 + lcol);
                rb[i] = *(const float4*)(W + (size_t)(n0 + row) * HDIM + k0 + 32 + lcol);
            }
        }
#pragma unroll
        for (int ks = 0; ks < 32; ks += 8) {
            unsigned a[2][4], b[8][2];
#pragma unroll
            for (int mi = 0; mi < 2; mi++) {
                int r = wm * 32 + mi * 16;
                a[mi][0] = As[(r + g) * 36 + ks + t];
                a[mi][1] = As[(r + g + 8) * 36 + ks + t];
                a[mi][2] = As[(r + g) * 36 + ks + t + 4];
                a[mi][3] = As[(r + g + 8) * 36 + ks + t + 4];
            }
#pragma unroll
            for (int ni = 0; ni < 8; ni++) {
                int c = wn * 64 + ni * 8;
                b[ni][0] = Bs[(c + g) * 36 + ks + t];
                b[ni][1] = Bs[(c + g) * 36 + ks + t + 4];
            }
#pragma unroll
            for (int mi = 0; mi < 2; mi++)
#pragma unroll
                for (int ni = 0; ni < 8; ni++)
                    mma8(acc[mi][ni], a[mi], b[ni]);
        }
        __syncthreads();
    }
#pragma unroll
    for (int mi = 0; mi < 2; mi++) {
#pragma unroll
        for (int h = 0; h < 2; h++) {
            int r = m0 + wm * 32 + mi * 16 + g + h * 8;
#pragma unroll
            for (int ni = 0; ni < 8; ni++) {
                int c = n0 + wn * 64 + ni * 8 + 2 * t;
                float v0 = fmaxf(acc[mi][ni][h * 2 + 0] + bias[c], 0.f);
                float v1 = fmaxf(acc[mi][ni][h * 2 + 1] + bias[c + 1], 0.f);
                *(float2*)(C + (size_t)r * HDIM + c) = make_float2(v0, v1);
            }
        }
    }
}

// ---------------------------------------------------------------------------
// Fused kernel. One CTA (256 threads) per 64-row block.
// smem (unsigned words): outs[64*260] | qs[64*260] | ks[64*260] | ws[256*20] | offs[32]
// fulls (4288 floats) aliases outs after q/k are built.
// ---------------------------------------------------------------------------
constexpr int OS = 260;       // stride for outs/qs/ks  (260 % 32 == 4 -> conflict-free)
constexpr int WST = 20;       // ws stride              (20 % 32 == 4)
constexpr int SM_OUTS = 0;
constexpr int SM_QS   = 64 * OS;
constexpr int SM_KS   = 2 * 64 * OS;
constexpr int SM_WS   = 3 * 64 * OS;
constexpr int SM_OFFS = 3 * 64 * OS + 256 * WST;
constexpr int SM_WORDS = SM_OFFS + 32;

// GEMM pass: dst[64,256] = tf32(outs @ W^T + bias). Warp tile 16x128 (4x2 warps).
__device__ __forceinline__ void qk_gemm(const unsigned* __restrict__ outs,
                                        unsigned* __restrict__ ws,
                                        unsigned* __restrict__ dst,
                                        const float* __restrict__ W,
                                        const float* __restrict__ bias,
                                        int tid, int wm, int wn, int g, int t) {
    float acc[16][4];
#pragma unroll
    for (int i = 0; i < 16; i++)
#pragma unroll
        for (int j = 0; j < 4; j++) acc[i][j] = 0.f;

    float4 st[4];
#pragma unroll
    for (int i = 0; i < 4; i++) {
        int j = tid + 256 * i;
        st[i] = *(const float4*)(W + (size_t)(j >> 2) * HDIM + (j & 3) * 4);
    }

    for (int k0 = 0; k0 < HDIM; k0 += 16) {
#pragma unroll
        for (int i = 0; i < 4; i++) {
            int j = tid + 256 * i;
            *(uint4*)&ws[(j >> 2) * WST + (j & 3) * 4] =
                make_uint4(f2tf(st[i].x), f2tf(st[i].y), f2tf(st[i].z), f2tf(st[i].w));
        }
        __syncthreads();
        if (k0 + 16 < HDIM) {
#pragma unroll
            for (int i = 0; i < 4; i++) {
                int j = tid + 256 * i;
                st[i] = *(const float4*)(W + (size_t)(j >> 2) * HDIM + k0 + 16 + (j & 3) * 4);
            }
        }
#pragma unroll
        for (int ks = 0; ks < 16; ks += 8) {
            unsigned a[4];
            int r = wm * 16;
            a[0] = outs[(r + g) * OS + k0 + ks + t];
            a[1] = outs[(r + g + 8) * OS + k0 + ks + t];
            a[2] = outs[(r + g) * OS + k0 + ks + t + 4];
            a[3] = outs[(r + g + 8) * OS + k0 + ks + t + 4];
#pragma unroll
            for (int ni = 0; ni < 16; ni++) {
                unsigned bb[2];
                int c = wn * 128 + ni * 8;
                bb[0] = ws[(c + g) * WST + ks + t];
                bb[1] = ws[(c + g) * WST + ks + t + 4];
                mma8(acc[ni], a, bb);
            }
        }
        __syncthreads();
    }
    // epilogue: bias, tf32, store
#pragma unroll
    for (int ni = 0; ni < 16; ni++) {
        int c = wn * 128 + ni * 8 + 2 * t;
        int r = wm * 16 + g;
        float bc0 = bias[c], bc1 = bias[c + 1];
        dst[r * OS + c]           = f2tf(acc[ni][0] + bc0);
        dst[r * OS + c + 1]       = f2tf(acc[ni][1] + bc1);
        dst[(r + 8) * OS + c]     = f2tf(acc[ni][2] + bc0);
        dst[(r + 8) * OS + c + 1] = f2tf(acc[ni][3] + bc1);
    }
}

__global__ __launch_bounds__(256, 1)
void fused_kernel(const float* __restrict__ Of,
                  const float* __restrict__ w2, const float* __restrict__ b2,
                  const float* __restrict__ w3, const float* __restrict__ b3,
                  const float* __restrict__ w4, const int* __restrict__ gidx,
                  float* __restrict__ out) {
    extern __shared__ unsigned sm[];
    unsigned* outs = sm + SM_OUTS;
    unsigned* qs   = sm + SM_QS;
    unsigned* kss  = sm + SM_KS;
    unsigned* ws   = sm + SM_WS;
    float* offs_sm = (float*)(sm + SM_OFFS);
    float* fulls   = (float*)outs;     // alias: outs dead after q/k built

    const int b = blockIdx.x;
    const int tid = threadIdx.x;
    const float* og = Of + (size_t)b * 64 * HDIM;

    // load out block -> outs (tf32)
    for (int i = tid * 4; i < 64 * HDIM; i += 256 * 4) {
        int row = i >> 8, col = i & 255;
        float4 v = *(const float4*)(og + i);
        *(uint4*)&outs[row * OS + col] =
            make_uint4(f2tf(v.x), f2tf(v.y), f2tf(v.z), f2tf(v.w));
    }
    __syncthreads();

    const int warp = tid >> 5, lane = tid & 31;
    const int g = lane >> 2, t = lane & 3;
    const int wm = warp >> 1, wn = warp & 1;

    qk_gemm(outs, ws, qs,  w2, b2, tid, wm, wn, g, t);
    qk_gemm(outs, ws, kss, w3, b3, tid, wm, wn, g, t);
    __syncthreads();   // q/k visible to all warps

    // ---- logits = q @ k^T * SCALE  (warp tile 16x32, 4x2 warps) ----
    float acc[4][4];
#pragma unroll
    for (int i = 0; i < 4; i++)
#pragma unroll
        for (int j = 0; j < 4; j++) acc[i][j] = 0.f;

    for (int k8 = 0; k8 < HDIM; k8 += 8) {
        unsigned a[4], bb[4][2];
        int r = wm * 16;
        a[0] = qs[(r + g) * OS + k8 + t];
        a[1] = qs[(r + g + 8) * OS + k8 + t];
        a[2] = qs[(r + g) * OS + k8 + t + 4];
        a[3] = qs[(r + g + 8) * OS + k8 + t + 4];
#pragma unroll
        for (int ni = 0; ni < 4; ni++) {
            int c = wn * 32 + ni * 8;
            bb[ni][0] = kss[(c + g) * OS + k8 + t];
            bb[ni][1] = kss[(c + g) * OS + k8 + t + 4];
        }
#pragma unroll
        for (int ni = 0; ni < 4; ni++) mma8(acc[ni], a, bb[ni]);
    }
    __syncthreads();   // everyone done reading outs-alias region? (fulls writes next)
#pragma unroll
    for (int ni = 0; ni < 4; ni++) {
        int c = wn * 32 + ni * 8 + 2 * t;
        int r0 = wm * 16 + g;
        fulls[r0 * 64 + c]           = acc[ni][0] * PSCALE;
        fulls[r0 * 64 + c + 1]       = acc[ni][1] * PSCALE;
        fulls[(r0 + 8) * 64 + c]     = acc[ni][2] * PSCALE;
        fulls[(r0 + 8) * 64 + c + 1] = acc[ni][3] * PSCALE;
    }
    __syncthreads();

    // ---- promo offsets: offs[p][s] = dot(k[56+s], w4[p]) ----
    if (warp == 0) {
        int p = lane >> 3, s = lane & 7;
        const float* w4r = w4 + p * HDIM;
        const unsigned* kr = &kss[(56 + s) * OS];
        float sum = 0.f;
#pragma unroll 8
        for (int hh = 0; hh < HDIM; hh++)
            sum += __uint_as_float(kr[hh]) * w4r[hh];
        offs_sm[lane] = sum;
    }
    __syncthreads();

    if (tid < 192) {
        int qq = tid / 24, rr = tid % 24, s = rr / 3, p = rr % 3;
        fulls[4096 + tid] = offs_sm[p * 8 + s] + offs_sm[24 + s]
                          + fulls[(48 + qq) * 64 + 56 + s];
    }
    __syncthreads();

    // ---- gather ----
    float* ob = out + (size_t)b * 1858;
    for (int i = tid; i < 1858; i += 256) ob[i] = fulls[gidx[i]];
}

// ---------------------------------------------------------------------------
extern "C" void kernel_launch(void* const* d_in, const int* in_sizes, int n_in,
                              void* d_out, int out_size) {
    const float* x  = (const float*)d_in[0];
    const float* w1 = (const float*)d_in[1];
    const float* b1 = (const float*)d_in[2];
    const float* w2 = (const float*)d_in[3];
    const float* b2 = (const float*)d_in[4];
    const float* w3 = (const float*)d_in[5];
    const float* b3 = (const float*)d_in[6];
    const float* w4 = (const float*)d_in[7];
    const int*   gi = (const int*)d_in[8];
    float* out = (float*)d_out;

    const int M = in_sizes[0] / HDIM;     // 262144
    const int nblk = M / 64;              // 4096

    float* o;
    cudaGetSymbolAddress((void**)&o, g_out);

    dim3 gg(HDIM / 128, M / 128);
    gemm1_kernel<<<gg, 256>>>(x, w1, b1, o);

    size_t shmem = (size_t)SM_WORDS * sizeof(unsigned);   // ~220 KB
    static bool attr_set = false;
    if (!attr_set) {
        cudaFuncSetAttribute((const void*)fused_kernel,
                             cudaFuncAttributeMaxDynamicSharedMemorySize, (int)shmem);
        attr_set = true;
    }
    fused_kernel<<<nblk, 256, shmem>>>(o, w2, b2, w3, b3, w4, gi, out);
}